// round 6
// baseline (speedup 1.0000x reference)
#include <cuda_runtime.h>

// BallPredictorGNN — sparse dependency cone + linear-GAT factorization.
// out depends only on node N-1 ("ball").
//   logits:  alpha_s1[v] = x[v] . (W1 @ a_src1) = x[v] . was[:,h]
//   layer1:  out1[v]     = (sum_j alpha_j x[src_j]) @ W1  (aggregate then project)
//   layer2:  alpha_s2[v] = r1[v] . w2s ; out2(ball) = (sum alpha r1[src]) @ W2
// Kernels: memset(state) -> pass1+prep -> pass2 -> agg1 -> final

#define NMAX      20480
#define FIN       128
#define H1C       256
#define C2        64
#define SRCA_CAP  1024
#define EB_CAP    65536
#define LIST_CAP  4096
#define DEG_CAP   512

struct ResetState {                 // zeroed by cudaMemsetAsync every call
    int need1[NMAX];
    int cntA, cntB, cnt1;
};
__device__ ResetState g_st;

__device__ int   g_srcA[SRCA_CAP];
__device__ int   g_srcB[EB_CAP];
__device__ int   g_dstB[EB_CAP];
__device__ int   g_list1[LIST_CAP];
__device__ float g_was[FIN * 4];    // [f*4+h]
__device__ float g_wad[FIN * 4];
__device__ float g_w2s[H1C], g_w2d[H1C];
__device__ float g_r1[(size_t)NMAX * H1C];
__device__ float g_as2[NMAX], g_ad2[NMAX];

__device__ __forceinline__ void mark_need1(int v) {
    if (atomicExch(&g_st.need1[v], 1) == 0) {
        int p = atomicAdd(&g_st.cnt1, 1);
        if (p < LIST_CAP) g_list1[p] = v;
    }
}

// blocks 0-7: was/wad; blocks 8,9: w2s/w2d; blocks 10+: scan dst column for ball
__global__ void k_pass1(const int* __restrict__ ei, int E, int ball, int N,
                        const float* __restrict__ W1,
                        const float* __restrict__ a_src1, const float* __restrict__ a_dst1,
                        const float* __restrict__ W2,
                        const float* __restrict__ a_src2, const float* __restrict__ a_dst2) {
    const int b = blockIdx.x, t = threadIdx.x;
    const int w = t >> 5, l = t & 31;
    if (b == 0 && t == 0) mark_need1(ball);
    if (b < 8) {
        __shared__ float s_red[16];
        int h = t >> 6, c = t & 63;
        float as = a_src1[h * 64 + c], ad = a_dst1[h * 64 + c];
        for (int f = b * 16; f < b * 16 + 16; f++) {
            float wv = W1[f * H1C + t];
            float ps = wv * as, pd = wv * ad;
#pragma unroll
            for (int o = 16; o; o >>= 1) {
                ps += __shfl_down_sync(~0u, ps, o);
                pd += __shfl_down_sync(~0u, pd, o);
            }
            if (l == 0) { s_red[w] = ps; s_red[8 + w] = pd; }
            __syncthreads();
            if (t < 4) {
                g_was[f * 4 + t] = s_red[2 * t] + s_red[2 * t + 1];
                g_wad[f * 4 + t] = s_red[8 + 2 * t] + s_red[8 + 2 * t + 1];
            }
            __syncthreads();
        }
        return;
    }
    if (b == 8 || b == 9) {
        const float* av = (b == 8) ? a_src2 : a_dst2;
        float s = 0.f;
        for (int c = 0; c < C2; c++) s += W2[t * C2 + c] * av[c];
        if (b == 8) g_w2s[t] = s; else g_w2d[t] = s;
        return;
    }
    const int nq = (E + 3) >> 2;
    const int* dcol = ei + E;
    const int nscan = (gridDim.x - 10) * 256;
    for (int q = (b - 10) * 256 + t; q < nq; q += nscan) {
        int base = q * 4;
        int d[4];
        if (base + 4 <= E) {
            int4 v4 = *reinterpret_cast<const int4*>(dcol + base);
            d[0] = v4.x; d[1] = v4.y; d[2] = v4.z; d[3] = v4.w;
        } else {
            for (int k = 0; k < 4; k++) d[k] = (base + k < E) ? dcol[base + k] : -1;
        }
#pragma unroll
        for (int k = 0; k < 4; k++) {
            if (d[k] == ball) {
                int src = ei[base + k];
                if ((unsigned)src >= (unsigned)N) continue;
                int p = atomicAdd(&g_st.cntA, 1);
                if (p < SRCA_CAP) g_srcA[p] = src;
                mark_need1(src);
            }
        }
    }
}

__global__ void k_pass2(const int* __restrict__ ei, int E, int N) {
    const int nq = (E + 3) >> 2;
    const int* dcol = ei + E;
    int q = blockIdx.x * blockDim.x + threadIdx.x;
    if (q >= nq) return;
    int base = q * 4;
    int d[4];
    if (base + 4 <= E) {
        int4 v4 = *reinterpret_cast<const int4*>(dcol + base);
        d[0] = v4.x; d[1] = v4.y; d[2] = v4.z; d[3] = v4.w;
    } else {
        for (int k = 0; k < 4; k++) d[k] = (base + k < E) ? dcol[base + k] : -1;
    }
#pragma unroll
    for (int k = 0; k < 4; k++) {
        int dst = d[k];
        if ((unsigned)dst >= (unsigned)N) continue;
        if (g_st.need1[dst]) {
            int src = ei[base + k];
            if ((unsigned)src >= (unsigned)N) continue;
            int p = atomicAdd(&g_st.cntB, 1);
            if (p < EB_CAP) { g_srcB[p] = src; g_dstB[p] = dst; }
        }
    }
}

// One block per need1 node.
__global__ void k_agg1(const float* __restrict__ x, const float* __restrict__ W1,
                       const float* __restrict__ b1) {
    __shared__ float s_was[FIN * 4];
    __shared__ float s_wad[FIN * 4];
    __shared__ int   s_src[DEG_CAP];
    __shared__ float s_e[DEG_CAP * 4];
    __shared__ float s_xv[FIN];
    __shared__ float s_xagg[4 * FIN];
    __shared__ float s_r1[H1C];
    __shared__ float s_adv[4];
    __shared__ float s_inv[4];
    __shared__ int   s_cnt;
    const int t = threadIdx.x, w = t >> 5, l = t & 31;
    const int n1 = min(g_st.cnt1, LIST_CAP);
    if (blockIdx.x >= n1) return;
    const int cb = min(g_st.cntB, EB_CAP);
    for (int i = t; i < FIN * 4; i += 256) { s_was[i] = g_was[i]; s_wad[i] = g_wad[i]; }

    for (int it = blockIdx.x; it < n1; it += gridDim.x) {
        int v = g_list1[it];
        if (t == 0) s_cnt = 0;
        if (t < FIN) s_xv[t] = x[(size_t)v * FIN + t];
        __syncthreads();
        for (int j = t; j < cb; j += 256) {
            if (g_dstB[j] == v) {
                int p = atomicAdd(&s_cnt, 1);
                if (p < DEG_CAP - 1) s_src[p] = g_srcB[j];
            }
        }
        __syncthreads();
        if (t == 0) {
            int p = min(s_cnt, DEG_CAP - 1);
            s_src[p] = v;                 // appended self-loop (matches reference)
            s_cnt = p + 1;
        }
        if (w < 4) {                      // dst logits
            float p = 0.f;
            for (int f = l; f < FIN; f += 32) p += s_xv[f] * s_wad[f * 4 + w];
#pragma unroll
            for (int o = 16; o; o >>= 1) p += __shfl_down_sync(~0u, p, o);
            if (l == 0) s_adv[w] = p;
        }
        __syncthreads();
        const int n = s_cnt;
        for (int j = w; j < n; j += 8) {  // src logits, warp per edge
            const float4 xv4 = reinterpret_cast<const float4*>(
                                   x + (size_t)s_src[j] * FIN)[l];
            float ph0 = 0.f, ph1 = 0.f, ph2 = 0.f, ph3 = 0.f;
            const float xs[4] = {xv4.x, xv4.y, xv4.z, xv4.w};
#pragma unroll
            for (int k = 0; k < 4; k++) {
                int f = 4 * l + k;
                ph0 += xs[k] * s_was[f * 4 + 0];
                ph1 += xs[k] * s_was[f * 4 + 1];
                ph2 += xs[k] * s_was[f * 4 + 2];
                ph3 += xs[k] * s_was[f * 4 + 3];
            }
#pragma unroll
            for (int o = 16; o; o >>= 1) {
                ph0 += __shfl_down_sync(~0u, ph0, o);
                ph1 += __shfl_down_sync(~0u, ph1, o);
                ph2 += __shfl_down_sync(~0u, ph2, o);
                ph3 += __shfl_down_sync(~0u, ph3, o);
            }
            if (l == 0) {
                float e0 = ph0 + s_adv[0], e1 = ph1 + s_adv[1];
                float e2 = ph2 + s_adv[2], e3 = ph3 + s_adv[3];
                s_e[j * 4 + 0] = (e0 > 0.f) ? e0 : 0.2f * e0;
                s_e[j * 4 + 1] = (e1 > 0.f) ? e1 : 0.2f * e1;
                s_e[j * 4 + 2] = (e2 > 0.f) ? e2 : 0.2f * e2;
                s_e[j * 4 + 3] = (e3 > 0.f) ? e3 : 0.2f * e3;
            }
        }
        __syncthreads();
        if (t < 4) {                      // stable softmax per head
            float m = -1e30f;
            for (int j = 0; j < n; j++) m = fmaxf(m, s_e[j * 4 + t]);
            float s = 0.f;
            for (int j = 0; j < n; j++) {
                float ww = expf(s_e[j * 4 + t] - m);
                s_e[j * 4 + t] = ww; s += ww;
            }
            s_inv[t] = 1.f / (s + 1e-16f);
        }
        __syncthreads();
        if (t < FIN) {                    // xagg, 4-way unrolled gather (MLP=4)
            float a0 = 0.f, a1 = 0.f, a2 = 0.f, a3 = 0.f;
            int j = 0;
            for (; j + 4 <= n; j += 4) {
                float x0 = x[(size_t)s_src[j + 0] * FIN + t];
                float x1 = x[(size_t)s_src[j + 1] * FIN + t];
                float x2 = x[(size_t)s_src[j + 2] * FIN + t];
                float x3 = x[(size_t)s_src[j + 3] * FIN + t];
                a0 += s_e[(j+0)*4+0]*x0 + s_e[(j+1)*4+0]*x1 + s_e[(j+2)*4+0]*x2 + s_e[(j+3)*4+0]*x3;
                a1 += s_e[(j+0)*4+1]*x0 + s_e[(j+1)*4+1]*x1 + s_e[(j+2)*4+1]*x2 + s_e[(j+3)*4+1]*x3;
                a2 += s_e[(j+0)*4+2]*x0 + s_e[(j+1)*4+2]*x1 + s_e[(j+2)*4+2]*x2 + s_e[(j+3)*4+2]*x3;
                a3 += s_e[(j+0)*4+3]*x0 + s_e[(j+1)*4+3]*x1 + s_e[(j+2)*4+3]*x2 + s_e[(j+3)*4+3]*x3;
            }
            for (; j < n; j++) {
                float xv = x[(size_t)s_src[j] * FIN + t];
                a0 += s_e[j*4+0]*xv; a1 += s_e[j*4+1]*xv;
                a2 += s_e[j*4+2]*xv; a3 += s_e[j*4+3]*xv;
            }
            s_xagg[0 * FIN + t] = a0 * s_inv[0];
            s_xagg[1 * FIN + t] = a1 * s_inv[1];
            s_xagg[2 * FIN + t] = a2 * s_inv[2];
            s_xagg[3 * FIN + t] = a3 * s_inv[3];
        }
        __syncthreads();
        {                                 // project through W1
            const int h = t >> 6;
            float acc = 0.f;
#pragma unroll 8
            for (int f = 0; f < FIN; f++)
                acc += s_xagg[h * FIN + f] * W1[f * H1C + t];
            float r = fmaxf(acc + b1[t], 0.f);
            s_r1[t] = r;
            g_r1[(size_t)v * H1C + t] = r;
        }
        __syncthreads();
        if (w < 2) {                      // layer-2 logits
            const float* wv = w ? g_w2d : g_w2s;
            float p = 0.f;
            for (int k = l; k < H1C; k += 32) p += s_r1[k] * wv[k];
#pragma unroll
            for (int o = 16; o; o >>= 1) p += __shfl_down_sync(~0u, p, o);
            if (l == 0) { if (w) g_ad2[v] = p; else g_as2[v] = p; }
        }
        __syncthreads();
    }
}

__device__ __forceinline__ float block_reduce(float v, float* s_red, int t, bool is_max) {
    const int w = t >> 5, l = t & 31;
#pragma unroll
    for (int o = 16; o; o >>= 1) {
        float u = __shfl_down_sync(~0u, v, o);
        v = is_max ? fmaxf(v, u) : (v + u);
    }
    if (l == 0) s_red[w] = v;
    __syncthreads();
    if (t < 8) {
        v = s_red[t];
#pragma unroll
        for (int o = 4; o; o >>= 1) {
            float u = __shfl_down_sync(0xffu, v, o);
            v = is_max ? fmaxf(v, u) : (v + u);
        }
        if (t == 0) s_red[0] = v;
    }
    __syncthreads();
    return s_red[0];
}

// Single block: layer-2 softmax at ball, @W2, relu, MLP -> out[2]
__global__ void k_final(const float* __restrict__ W2, const float* __restrict__ b2,
                        const float* __restrict__ fc1_w, const float* __restrict__ fc1_b,
                        const float* __restrict__ fc2_w, const float* __restrict__ fc2_b,
                        float* __restrict__ out, int ball) {
    __shared__ int   s_idx[SRCA_CAP + 1];
    __shared__ float sw[SRCA_CAP + 1];
    __shared__ float s_ragg[H1C];
    __shared__ float s_o[C2];
    __shared__ float s_z[32];
    __shared__ float s_red[8];
    const int t = threadIdx.x;
    const int nA = min(g_st.cntA, SRCA_CAP);
    const int cnt = nA + 1;
    // stage indices (parallel, one round trip)
    for (int j = t; j < cnt; j += 256) s_idx[j] = (j < nA) ? g_srcA[j] : ball;
    __syncthreads();
    const float adv = g_ad2[ball];
    for (int j = t; j < cnt; j += 256) {
        float e = g_as2[s_idx[j]] + adv;
        sw[j] = (e > 0.f) ? e : 0.2f * e;
    }
    __syncthreads();
    // block-parallel stable softmax
    float lm = -1e30f;
    for (int j = t; j < cnt; j += 256) lm = fmaxf(lm, sw[j]);
    float m = block_reduce(lm, s_red, t, true);
    float ls = 0.f;
    for (int j = t; j < cnt; j += 256) { float ww = expf(sw[j] - m); sw[j] = ww; ls += ww; }
    __syncthreads();   // sw writes done before reuse of s_red barrier pattern
    float ssum = block_reduce(ls, s_red, t, false);
    float sinv = 1.f / (ssum + 1e-16f);
    __syncthreads();
    {   // ragg gather, 4-way unrolled (independent loads, L2-hot rows)
        float acc = 0.f;
        int j = 0;
        for (; j + 4 <= cnt; j += 4) {
            float r0 = g_r1[(size_t)s_idx[j + 0] * H1C + t];
            float r1 = g_r1[(size_t)s_idx[j + 1] * H1C + t];
            float r2 = g_r1[(size_t)s_idx[j + 2] * H1C + t];
            float r3 = g_r1[(size_t)s_idx[j + 3] * H1C + t];
            acc += sw[j]*r0 + sw[j+1]*r1 + sw[j+2]*r2 + sw[j+3]*r3;
        }
        for (; j < cnt; j++) acc += sw[j] * g_r1[(size_t)s_idx[j] * H1C + t];
        s_ragg[t] = acc * sinv;
    }
    __syncthreads();
    if (t < C2) {
        float acc = 0.f;
#pragma unroll 8
        for (int k = 0; k < H1C; k++) acc += s_ragg[k] * W2[k * C2 + t];
        s_o[t] = fmaxf(acc + b2[t], 0.f);
    }
    __syncthreads();
    if (t < 32) {
        float a = fc1_b[t];
        for (int k = 0; k < C2; k++) a += s_o[k] * fc1_w[k * 32 + t];
        s_z[t] = fmaxf(a, 0.f);
    }
    __syncthreads();
    if (t < 2) {
        float a = fc2_b[t];
        for (int k = 0; k < 32; k++) a += s_z[k] * fc2_w[k * 2 + t];
        out[t] = a;
    }
}

extern "C" void kernel_launch(void* const* d_in, const int* in_sizes, int n_in,
                              void* d_out, int out_size) {
    const float* x      = (const float*)d_in[0];
    const int*   ei     = (const int*)d_in[1];   // int32 (JAX x64-disabled)
    const float* W1     = (const float*)d_in[2];
    const float* a_src1 = (const float*)d_in[3];
    const float* a_dst1 = (const float*)d_in[4];
    const float* b1     = (const float*)d_in[5];
    const float* W2     = (const float*)d_in[6];
    const float* a_src2 = (const float*)d_in[7];
    const float* a_dst2 = (const float*)d_in[8];
    const float* b2     = (const float*)d_in[9];
    const float* fc1_w  = (const float*)d_in[10];
    const float* fc1_b  = (const float*)d_in[11];
    const float* fc2_w  = (const float*)d_in[12];
    const float* fc2_b  = (const float*)d_in[13];

    int N = in_sizes[0] / FIN;   // 20000
    int E = in_sizes[1] / 2;     // 640000
    int ball = N - 1;
    int EQ = (E + 3) / 4;

    void* st_addr = nullptr;
    cudaGetSymbolAddress(&st_addr, g_st);
    cudaMemsetAsync(st_addr, 0, sizeof(ResetState), 0);

    k_pass1<<<10 + (EQ + 255) / 256, 256>>>(ei, E, ball, N, W1, a_src1, a_dst1,
                                            W2, a_src2, a_dst2);
    k_pass2<<<(EQ + 255) / 256, 256>>>(ei, E, N);
    k_agg1 <<<64, 256>>>(x, W1, b1);
    k_final<<<1, 256>>>(W2, b2, fc1_w, fc1_b, fc2_w, fc2_b, (float*)d_out, ball);
}

// round 7
// speedup vs baseline: 1.3592x; 1.3592x over previous
#include <cuda_runtime.h>

// BallPredictorGNN — sparse dependency cone + linear-GAT factorization.
// out depends only on node N-1 ("ball").
//   layer1 logits: alpha_s1[v] = x[v] . (W1 @ a_src1) = x[v] . was[:,h]
//   layer1 out:    r1[v] = relu( (sum_j alpha_j x[src_j]) @ W1 + b1 )
//   layer2 feat:   g2[v] = r1[v] @ W2        (computed per node, in parallel)
//   layer2 logits: as2[v] = g2[v] . a_src2   (exact reference math)
//   output:        out2(ball) = sum_j alpha_j g2[src_j] + b2 -> relu -> MLP
// Kernels: memset(state) -> pass1(+was/wad prep) -> pass2 -> agg1 -> final

#define NMAX      20480
#define FIN       128
#define H1C       256
#define C2        64
#define SRCA_CAP  1024
#define EB_CAP    65536
#define LIST_CAP  4096
#define DEG_CAP   512

struct ResetState {                 // zeroed by cudaMemsetAsync every call
    int need1[NMAX];
    int cntA, cntB, cnt1;
};
__device__ ResetState g_st;

__device__ int   g_srcA[SRCA_CAP];
__device__ int   g_srcB[EB_CAP];
__device__ int   g_dstB[EB_CAP];
__device__ int   g_list1[LIST_CAP];
__device__ float g_was[FIN * 4];    // [f*4+h]
__device__ float g_wad[FIN * 4];
__device__ float g_g2[(size_t)NMAX * C2];    // r1 @ W2 per need1 node
__device__ float g_as2[NMAX], g_ad2[NMAX];

__device__ __forceinline__ void mark_need1(int v) {
    if (atomicExch(&g_st.need1[v], 1) == 0) {
        int p = atomicAdd(&g_st.cnt1, 1);
        if (p < LIST_CAP) g_list1[p] = v;
    }
}

// blocks 0-7: was/wad prep; blocks 8+: scan dst column for edges into ball
__global__ void k_pass1(const int* __restrict__ ei, int E, int ball, int N,
                        const float* __restrict__ W1,
                        const float* __restrict__ a_src1, const float* __restrict__ a_dst1) {
    const int b = blockIdx.x, t = threadIdx.x;
    const int w = t >> 5, l = t & 31;
    if (b == 0 && t == 0) mark_need1(ball);
    if (b < 8) {
        __shared__ float s_red[16];
        int h = t >> 6, c = t & 63;
        float as = a_src1[h * 64 + c], ad = a_dst1[h * 64 + c];
        for (int f = b * 16; f < b * 16 + 16; f++) {
            float wv = W1[f * H1C + t];
            float ps = wv * as, pd = wv * ad;
#pragma unroll
            for (int o = 16; o; o >>= 1) {
                ps += __shfl_down_sync(~0u, ps, o);
                pd += __shfl_down_sync(~0u, pd, o);
            }
            if (l == 0) { s_red[w] = ps; s_red[8 + w] = pd; }
            __syncthreads();
            if (t < 4) {
                g_was[f * 4 + t] = s_red[2 * t] + s_red[2 * t + 1];
                g_wad[f * 4 + t] = s_red[8 + 2 * t] + s_red[8 + 2 * t + 1];
            }
            __syncthreads();
        }
        return;
    }
    const int nq = (E + 3) >> 2;
    const int* dcol = ei + E;
    const int nscan = (gridDim.x - 8) * 256;
    for (int q = (b - 8) * 256 + t; q < nq; q += nscan) {
        int base = q * 4;
        int d[4];
        if (base + 4 <= E) {
            int4 v4 = *reinterpret_cast<const int4*>(dcol + base);
            d[0] = v4.x; d[1] = v4.y; d[2] = v4.z; d[3] = v4.w;
        } else {
            for (int k = 0; k < 4; k++) d[k] = (base + k < E) ? dcol[base + k] : -1;
        }
#pragma unroll
        for (int k = 0; k < 4; k++) {
            if (d[k] == ball) {
                int src = ei[base + k];
                if ((unsigned)src >= (unsigned)N) continue;
                int p = atomicAdd(&g_st.cntA, 1);
                if (p < SRCA_CAP) g_srcA[p] = src;
                mark_need1(src);
            }
        }
    }
}

__global__ void k_pass2(const int* __restrict__ ei, int E, int N) {
    const int nq = (E + 3) >> 2;
    const int* dcol = ei + E;
    int q = blockIdx.x * blockDim.x + threadIdx.x;
    if (q >= nq) return;
    int base = q * 4;
    int d[4];
    if (base + 4 <= E) {
        int4 v4 = *reinterpret_cast<const int4*>(dcol + base);
        d[0] = v4.x; d[1] = v4.y; d[2] = v4.z; d[3] = v4.w;
    } else {
        for (int k = 0; k < 4; k++) d[k] = (base + k < E) ? dcol[base + k] : -1;
    }
#pragma unroll
    for (int k = 0; k < 4; k++) {
        int dst = d[k];
        if ((unsigned)dst >= (unsigned)N) continue;
        if (g_st.need1[dst]) {
            int src = ei[base + k];
            if ((unsigned)src >= (unsigned)N) continue;
            int p = atomicAdd(&g_st.cntB, 1);
            if (p < EB_CAP) { g_srcB[p] = src; g_dstB[p] = dst; }
        }
    }
}

// One block per need1 node: softmax over in-edges, aggregate x, project W1,
// relu -> r1, project W2 -> g2 (stored), layer-2 logits from g2.
__global__ void k_agg1(const float* __restrict__ x, const float* __restrict__ W1,
                       const float* __restrict__ b1, const float* __restrict__ W2,
                       const float* __restrict__ a_src2, const float* __restrict__ a_dst2) {
    __shared__ float s_was[FIN * 4];
    __shared__ float s_wad[FIN * 4];
    __shared__ int   s_src[DEG_CAP];
    __shared__ float s_e[DEG_CAP * 4];
    __shared__ float s_xv[FIN];
    __shared__ float s_xagg[4 * FIN];
    __shared__ float s_r1[H1C];
    __shared__ float s_part[4 * C2];
    __shared__ float s_g2[C2];
    __shared__ float s_adv[4];
    __shared__ float s_inv[4];
    __shared__ int   s_cnt;
    const int t = threadIdx.x, w = t >> 5, l = t & 31;
    const int n1 = min(g_st.cnt1, LIST_CAP);
    if (blockIdx.x >= n1) return;
    const int cb = min(g_st.cntB, EB_CAP);
    for (int i = t; i < FIN * 4; i += 256) { s_was[i] = g_was[i]; s_wad[i] = g_wad[i]; }

    for (int it = blockIdx.x; it < n1; it += gridDim.x) {
        int v = g_list1[it];
        if (t == 0) s_cnt = 0;
        if (t < FIN) s_xv[t] = x[(size_t)v * FIN + t];
        __syncthreads();
        for (int j = t; j < cb; j += 256) {
            if (g_dstB[j] == v) {
                int p = atomicAdd(&s_cnt, 1);
                if (p < DEG_CAP - 1) s_src[p] = g_srcB[j];
            }
        }
        __syncthreads();
        if (t == 0) {
            int p = min(s_cnt, DEG_CAP - 1);
            s_src[p] = v;                 // appended self-loop (matches reference)
            s_cnt = p + 1;
        }
        if (w < 4) {                      // dst logits: x[v] . wad[:,h]
            float p = 0.f;
            for (int f = l; f < FIN; f += 32) p += s_xv[f] * s_wad[f * 4 + w];
#pragma unroll
            for (int o = 16; o; o >>= 1) p += __shfl_down_sync(~0u, p, o);
            if (l == 0) s_adv[w] = p;
        }
        __syncthreads();
        const int n = s_cnt;
        for (int j = w; j < n; j += 8) {  // src logits, warp per edge
            const float4 xv4 = reinterpret_cast<const float4*>(
                                   x + (size_t)s_src[j] * FIN)[l];
            float ph0 = 0.f, ph1 = 0.f, ph2 = 0.f, ph3 = 0.f;
            const float xs[4] = {xv4.x, xv4.y, xv4.z, xv4.w};
#pragma unroll
            for (int k = 0; k < 4; k++) {
                int f = 4 * l + k;
                ph0 += xs[k] * s_was[f * 4 + 0];
                ph1 += xs[k] * s_was[f * 4 + 1];
                ph2 += xs[k] * s_was[f * 4 + 2];
                ph3 += xs[k] * s_was[f * 4 + 3];
            }
#pragma unroll
            for (int o = 16; o; o >>= 1) {
                ph0 += __shfl_down_sync(~0u, ph0, o);
                ph1 += __shfl_down_sync(~0u, ph1, o);
                ph2 += __shfl_down_sync(~0u, ph2, o);
                ph3 += __shfl_down_sync(~0u, ph3, o);
            }
            if (l == 0) {
                float e0 = ph0 + s_adv[0], e1 = ph1 + s_adv[1];
                float e2 = ph2 + s_adv[2], e3 = ph3 + s_adv[3];
                s_e[j * 4 + 0] = (e0 > 0.f) ? e0 : 0.2f * e0;   // leaky_relu 0.2
                s_e[j * 4 + 1] = (e1 > 0.f) ? e1 : 0.2f * e1;
                s_e[j * 4 + 2] = (e2 > 0.f) ? e2 : 0.2f * e2;
                s_e[j * 4 + 3] = (e3 > 0.f) ? e3 : 0.2f * e3;
            }
        }
        __syncthreads();
        if (t < 4) {                      // stable softmax per head
            float m = -1e30f;
            for (int j = 0; j < n; j++) m = fmaxf(m, s_e[j * 4 + t]);
            float s = 0.f;
            for (int j = 0; j < n; j++) {
                float ww = expf(s_e[j * 4 + t] - m);
                s_e[j * 4 + t] = ww; s += ww;
            }
            s_inv[t] = 1.f / (s + 1e-16f);
        }
        __syncthreads();
        if (t < FIN) {                    // xagg, 4-way unrolled gather
            float a0 = 0.f, a1 = 0.f, a2 = 0.f, a3 = 0.f;
            int j = 0;
            for (; j + 4 <= n; j += 4) {
                float x0 = x[(size_t)s_src[j + 0] * FIN + t];
                float x1 = x[(size_t)s_src[j + 1] * FIN + t];
                float x2 = x[(size_t)s_src[j + 2] * FIN + t];
                float x3 = x[(size_t)s_src[j + 3] * FIN + t];
                a0 += s_e[(j+0)*4+0]*x0 + s_e[(j+1)*4+0]*x1 + s_e[(j+2)*4+0]*x2 + s_e[(j+3)*4+0]*x3;
                a1 += s_e[(j+0)*4+1]*x0 + s_e[(j+1)*4+1]*x1 + s_e[(j+2)*4+1]*x2 + s_e[(j+3)*4+1]*x3;
                a2 += s_e[(j+0)*4+2]*x0 + s_e[(j+1)*4+2]*x1 + s_e[(j+2)*4+2]*x2 + s_e[(j+3)*4+2]*x3;
                a3 += s_e[(j+0)*4+3]*x0 + s_e[(j+1)*4+3]*x1 + s_e[(j+2)*4+3]*x2 + s_e[(j+3)*4+3]*x3;
            }
            for (; j < n; j++) {
                float xv = x[(size_t)s_src[j] * FIN + t];
                a0 += s_e[j*4+0]*xv; a1 += s_e[j*4+1]*xv;
                a2 += s_e[j*4+2]*xv; a3 += s_e[j*4+3]*xv;
            }
            s_xagg[0 * FIN + t] = a0 * s_inv[0];
            s_xagg[1 * FIN + t] = a1 * s_inv[1];
            s_xagg[2 * FIN + t] = a2 * s_inv[2];
            s_xagg[3 * FIN + t] = a3 * s_inv[3];
        }
        __syncthreads();
        {                                 // project through W1 -> r1
            const int h = t >> 6;
            float acc = 0.f;
#pragma unroll 8
            for (int f = 0; f < FIN; f++)
                acc += s_xagg[h * FIN + f] * W1[f * H1C + t];
            s_r1[t] = fmaxf(acc + b1[t], 0.f);
        }
        __syncthreads();
        {                                 // g2 = r1 @ W2, 256 threads (4 k-chunks x 64 cols)
            const int c = t & 63, q = t >> 6;
            float p = 0.f;
#pragma unroll 16
            for (int k = q * 64; k < q * 64 + 64; k++)
                p += s_r1[k] * W2[k * C2 + c];
            s_part[q * C2 + c] = p;
        }
        __syncthreads();
        if (t < C2) {
            float g = s_part[t] + s_part[C2 + t] + s_part[2 * C2 + t] + s_part[3 * C2 + t];
            s_g2[t] = g;
            g_g2[(size_t)v * C2 + t] = g;
        }
        __syncthreads();
        if (w < 2) {                      // layer-2 logits: g2 . a_{src,dst}2
            const float* av = w ? a_dst2 : a_src2;
            float p = 0.f;
            p += s_g2[l] * av[l];
            p += s_g2[l + 32] * av[l + 32];
#pragma unroll
            for (int o = 16; o; o >>= 1) p += __shfl_down_sync(~0u, p, o);
            if (l == 0) { if (w) g_ad2[v] = p; else g_as2[v] = p; }
        }
        __syncthreads();
    }
}

__device__ __forceinline__ float block_reduce(float v, float* s_red, int t, bool is_max) {
    const int w = t >> 5, l = t & 31;
#pragma unroll
    for (int o = 16; o; o >>= 1) {
        float u = __shfl_down_sync(~0u, v, o);
        v = is_max ? fmaxf(v, u) : (v + u);
    }
    if (l == 0) s_red[w] = v;
    __syncthreads();
    if (t < 8) {
        v = s_red[t];
#pragma unroll
        for (int o = 4; o; o >>= 1) {
            float u = __shfl_down_sync(0xffu, v, o);
            v = is_max ? fmaxf(v, u) : (v + u);
        }
        if (t == 0) s_red[0] = v;
    }
    __syncthreads();
    return s_red[0];
}

// Single block: layer-2 softmax at ball, aggregate g2, relu, fc1+relu, fc2.
__global__ void k_final(const float* __restrict__ b2,
                        const float* __restrict__ fc1_w, const float* __restrict__ fc1_b,
                        const float* __restrict__ fc2_w, const float* __restrict__ fc2_b,
                        float* __restrict__ out, int ball) {
    __shared__ int   s_idx[SRCA_CAP + 1];
    __shared__ float sw[SRCA_CAP + 1];
    __shared__ float s_part[4 * C2];
    __shared__ float s_o[C2];
    __shared__ float s_p2[8 * 32];
    __shared__ float s_z[32];
    __shared__ float s_red[8];
    const int t = threadIdx.x;
    const int nA = min(g_st.cntA, SRCA_CAP);
    const int cnt = nA + 1;
    for (int j = t; j < cnt; j += 256) s_idx[j] = (j < nA) ? g_srcA[j] : ball;
    __syncthreads();
    const float adv = g_ad2[ball];
    for (int j = t; j < cnt; j += 256) {
        float e = g_as2[s_idx[j]] + adv;
        sw[j] = (e > 0.f) ? e : 0.2f * e;
    }
    __syncthreads();
    float lm = -1e30f;
    for (int j = t; j < cnt; j += 256) lm = fmaxf(lm, sw[j]);
    float m = block_reduce(lm, s_red, t, true);
    float ls = 0.f;
    for (int j = t; j < cnt; j += 256) { float ww = expf(sw[j] - m); sw[j] = ww; ls += ww; }
    __syncthreads();
    float ssum = block_reduce(ls, s_red, t, false);
    float sinv = 1.f / (ssum + 1e-16f);
    __syncthreads();
    {   // aggregate g2: 4 j-chunks x 64 cols, all 256 threads
        const int c = t & 63, q = t >> 6;
        float acc = 0.f;
        for (int j = q; j < cnt; j += 4)
            acc += sw[j] * g_g2[(size_t)s_idx[j] * C2 + c];
        s_part[q * C2 + c] = acc;
    }
    __syncthreads();
    if (t < C2) {
        float o = (s_part[t] + s_part[C2 + t] + s_part[2 * C2 + t] + s_part[3 * C2 + t])
                  * sinv + b2[t];
        s_o[t] = fmaxf(o, 0.f);
    }
    __syncthreads();
    {   // fc1: 8 k-chunks x 32 outputs
        const int o = t & 31, q = t >> 5;
        float p = 0.f;
#pragma unroll
        for (int k = q * 8; k < q * 8 + 8; k++) p += s_o[k] * fc1_w[k * 32 + o];
        s_p2[q * 32 + o] = p;
    }
    __syncthreads();
    if (t < 32) {
        float a = fc1_b[t];
#pragma unroll
        for (int q = 0; q < 8; q++) a += s_p2[q * 32 + t];
        s_z[t] = fmaxf(a, 0.f);
    }
    __syncthreads();
    if (t < 2) {
        float a = fc2_b[t];
        for (int k = 0; k < 32; k++) a += s_z[k] * fc2_w[k * 2 + t];
        out[t] = a;
    }
}

extern "C" void kernel_launch(void* const* d_in, const int* in_sizes, int n_in,
                              void* d_out, int out_size) {
    const float* x      = (const float*)d_in[0];
    const int*   ei     = (const int*)d_in[1];   // int32 (JAX x64-disabled)
    const float* W1     = (const float*)d_in[2];
    const float* a_src1 = (const float*)d_in[3];
    const float* a_dst1 = (const float*)d_in[4];
    const float* b1     = (const float*)d_in[5];
    const float* W2     = (const float*)d_in[6];
    const float* a_src2 = (const float*)d_in[7];
    const float* a_dst2 = (const float*)d_in[8];
    const float* b2     = (const float*)d_in[9];
    const float* fc1_w  = (const float*)d_in[10];
    const float* fc1_b  = (const float*)d_in[11];
    const float* fc2_w  = (const float*)d_in[12];
    const float* fc2_b  = (const float*)d_in[13];

    int N = in_sizes[0] / FIN;   // 20000
    int E = in_sizes[1] / 2;     // 640000
    int ball = N - 1;
    int EQ = (E + 3) / 4;

    void* st_addr = nullptr;
    cudaGetSymbolAddress(&st_addr, g_st);
    cudaMemsetAsync(st_addr, 0, sizeof(ResetState), 0);

    k_pass1<<<8 + (EQ + 255) / 256, 256>>>(ei, E, ball, N, W1, a_src1, a_dst1);
    k_pass2<<<(EQ + 255) / 256, 256>>>(ei, E, N);
    k_agg1 <<<64, 256>>>(x, W1, b1, W2, a_src2, a_dst2);
    k_final<<<1, 256>>>(b2, fc1_w, fc1_b, fc2_w, fc2_b, (float*)d_out, ball);
}